// round 15
// baseline (speedup 1.0000x reference)
#include <cuda_runtime.h>
#include <cuda_fp16.h>
#include <cstdint>

#define BATCH 8
#define CH    64
#define NPIX  4096

__device__ __align__(128) __half g_fq[BATCH*NPIX*CH]; // f*log2e [b][n][c]
__device__ __align__(128) __half g_gq[BATCH*NPIX*CH]; // g       [b][n][c]
__device__ __align__(128) __half g_hq[BATCH*CH*NPIX]; // h       [b][c][n]
__device__ __half g_S[(size_t)BATCH*NPIX*NPIX];       // s~ logits [b][i][j] fp16
__device__ float g_L[BATCH*NPIX];
__device__ __align__(128) uint8_t g_Wq[24576];
__device__ __align__(128) float   g_bias[192];

__device__ __forceinline__ uint32_t smem_u32(const void* p){
    uint32_t a; asm("{ .reg .u64 t; cvta.to.shared.u64 t, %1; cvt.u32.u64 %0, t; }":"=r"(a):"l"(p)); return a;
}
__device__ __forceinline__ uint32_t swz(uint32_t o){ return o ^ ((o>>3)&0x70); }
__device__ __forceinline__ float ex2(float x){
    float y; asm("ex2.approx.f32 %0, %1;":"=f"(y):"f"(x)); return y;
}
__device__ __forceinline__ float lg2(float x){
    float y; asm("lg2.approx.f32 %0, %1;":"=f"(y):"f"(x)); return y;
}
__device__ __forceinline__ uint32_t cvtpack(float lo, float hi){
    uint32_t r; asm("cvt.rn.f16x2.f32 %0, %1, %2;" : "=r"(r) : "f"(hi), "f"(lo)); return r;
}
__device__ __forceinline__ uint32_t sub2(uint32_t a, uint32_t b){
    uint32_t r; asm("sub.rn.f16x2 %0, %1, %2;" : "=r"(r) : "r"(a), "r"(b)); return r;
}
__device__ __forceinline__ uint32_t ex2h2(uint32_t a){
    uint32_t r; asm("ex2.approx.f16x2 %0, %1;" : "=r"(r) : "r"(a)); return r;
}
__device__ __forceinline__ float2 h2f2(uint32_t h){
    return __half22float2(*reinterpret_cast<const __half2*>(&h));
}
#define CP16(dst, src) asm volatile("cp.async.cg.shared.global [%0], [%1], 16;"::"r"(dst),"l"(src):"memory")
#define CPCOMMIT()     asm volatile("cp.async.commit_group;":::"memory")
#define CPWAIT(n)      asm volatile("cp.async.wait_group %0;"::"n"(n):"memory")

__device__ __forceinline__ void ldsm4(uint32_t r[4], uint32_t addr){
    asm volatile("ldmatrix.sync.aligned.m8n8.x4.shared.b16 {%0,%1,%2,%3},[%4];"
        : "=r"(r[0]),"=r"(r[1]),"=r"(r[2]),"=r"(r[3]) : "r"(addr));
}
__device__ __forceinline__ void ldsm4t(uint32_t r[4], uint32_t addr){
    asm volatile("ldmatrix.sync.aligned.m8n8.x4.trans.shared.b16 {%0,%1,%2,%3},[%4];"
        : "=r"(r[0]),"=r"(r[1]),"=r"(r[2]),"=r"(r[3]) : "r"(addr));
}
__device__ __forceinline__ void mma_f16(float d[4], const uint32_t a[4], const uint32_t b[2]){
    asm volatile("mma.sync.aligned.m16n8k16.row.col.f32.f16.f16.f32 "
        "{%0,%1,%2,%3},{%4,%5,%6,%7},{%8,%9},{%0,%1,%2,%3};"
        : "+f"(d[0]),"+f"(d[1]),"+f"(d[2]),"+f"(d[3])
        : "r"(a[0]),"r"(a[1]),"r"(a[2]),"r"(a[3]),"r"(b[0]),"r"(b[1]));
}
__device__ __forceinline__ void mma_h16(uint32_t d[2], const uint32_t a[4], const uint32_t b[2]){
    asm volatile("mma.sync.aligned.m16n8k16.row.col.f16.f16.f16.f16 "
        "{%0,%1},{%2,%3,%4,%5},{%6,%7},{%0,%1};"
        : "+r"(d[0]),"+r"(d[1])
        : "r"(a[0]),"r"(a[1]),"r"(a[2]),"r"(a[3]),"r"(b[0]),"r"(b[1]));
}

// ---------------- Stage 0: W/bias prep ---------------------------------------
__global__ __launch_bounds__(256) void prep_w(
    const float* __restrict__ Wf, const float* __restrict__ bf,
    const float* __restrict__ Wg, const float* __restrict__ bg,
    const float* __restrict__ Wh, const float* __restrict__ bh)
{
    const int t = threadIdx.x;
    for (int q = t; q < 3*4096; q += 256) {
        int mtx = q >> 12, idx = q & 4095;
        const float* Wsrc = (mtx==0)?Wf:((mtx==1)?Wg:Wh);
        float v = Wsrc[idx] * ((mtx==0) ? 1.44269504f : 1.0f);
        int o = idx >> 6, k = idx & 63;
        *(__half*)(g_Wq + mtx*8192u + swz(o*128 + k*2)) = __float2half_rn(v);
    }
    if (t < 192) {
        const float* bsrc = (t<64)?bf:((t<128)?bg:bh);
        g_bias[t] = bsrc[t&63] * ((t<64) ? 1.44269504f : 1.0f);
    }
}

// ---------------- Stage A: projections via HMMA; n-tile 64, 128 thr ----------
__global__ __launch_bounds__(128,4) void fgh_hmma(const float* __restrict__ x)
{
    extern __shared__ uint8_t dyn0[];
    uint8_t* A = (uint8_t*)(((uintptr_t)dyn0 + 1023) & ~(uintptr_t)1023);
    const uint32_t Au = smem_u32(A);
    const uint32_t BIAS=24576, SX=25600, STG=33792;

    const int t = threadIdx.x, lane = t&31, wid = t>>5;
    const int b = blockIdx.y, n0 = blockIdx.x*64;

    for (int q = t; q < 1536; q += 128) CP16(Au + q*16, (const char*)g_Wq + q*16);
    if (t < 48) CP16(Au + BIAS + t*16, (const char*)g_bias + t*16);
    CPCOMMIT();

    {
        int c = t>>1, half = t&1;
        const float* xr = x + ((size_t)b*CH + c)*NPIX + n0 + half*32;
#pragma unroll
        for (int u = 0; u < 16; u++) {
            float2 v = *(const float2*)(xr + 2*u);
            *(uint32_t*)(A + SX + swz((uint32_t)(c*128 + (half*32 + 2*u)*2))) = cvtpack(v.x, v.y);
        }
    }
    CPWAIT(0); __syncthreads();

    uint32_t ax[4][4];
    const int m0 = wid*16;
#pragma unroll
    for (int kk = 0; kk < 4; kk++) {
        int row = kk*16 + (lane&7) + ((lane>>4)<<3);
        int col = m0 + ((lane>>3)&1)*8;
        ldsm4t(ax[kk], Au + SX + swz((uint32_t)(row*128 + col*2)));
    }
    const float* bias = (const float*)(A+BIAS);

#pragma unroll 1
    for (int mtx = 0; mtx < 3; mtx++) {
        float acc[8][4];
#pragma unroll
        for (int ob = 0; ob < 8; ob++) {
            float b0 = bias[mtx*64 + ob*8 + (lane&3)*2];
            float b1 = bias[mtx*64 + ob*8 + (lane&3)*2 + 1];
            acc[ob][0]=b0; acc[ob][1]=b1; acc[ob][2]=b0; acc[ob][3]=b1;
        }
#pragma unroll
        for (int kk = 0; kk < 4; kk++) {
#pragma unroll
            for (int op = 0; op < 4; op++) {
                uint32_t off = swz((uint32_t)((op*16 + ((lane>>4)&1)*8 + (lane&7))*128
                                              + kk*32 + ((lane>>3)&1)*16));
                uint32_t bw[4];
                ldsm4(bw, Au + mtx*8192u + off);
                mma_f16(acc[2*op],   ax[kk], &bw[0]);
                mma_f16(acc[2*op+1], ax[kk], &bw[2]);
            }
        }
        __syncthreads();
#pragma unroll
        for (int ob = 0; ob < 8; ob++) {
            int o = ob*8 + (lane&3)*2, r = lane>>2;
            *(uint32_t*)(A + STG + swz((uint32_t)((m0+r)*128   + o*2))) = cvtpack(acc[ob][0], acc[ob][1]);
            *(uint32_t*)(A + STG + swz((uint32_t)((m0+r+8)*128 + o*2))) = cvtpack(acc[ob][2], acc[ob][3]);
        }
        __syncthreads();
        if (mtx < 2) {
            char* dst = (char*)(((mtx==0)?g_fq:g_gq) + ((size_t)b*NPIX + n0)*CH);
#pragma unroll
            for (int q = t; q < 512; q += 128) {
                int4 v = *(int4*)(A + STG + swz((uint32_t)(q*16)));
                *(int4*)(dst + q*16) = v;
            }
        } else {
            int c = t>>1, half = t&1;
            __half* dst = g_hq + ((size_t)b*CH + c)*NPIX + n0;
#pragma unroll
            for (int u = 0; u < 16; u++) {
                int n = half*32 + 2*u;
                uint32_t e0 = *(uint16_t*)(A + STG + swz((uint32_t)(n*128 + c*2)));
                uint32_t e1 = *(uint16_t*)(A + STG + swz((uint32_t)((n+1)*128 + c*2)));
                *(uint32_t*)(dst + n) = e0 | (e1<<16);
            }
        }
    }
}

// ---------------- Pass 1: L[i] + store s~; 4 warps x 16 i, j-tile 128 --------
// grid (64, 8), 128 threads. smem: F 8K | G dbl 2x16K | SG 16K = 56K. 3 CTAs/SM.
__global__ __launch_bounds__(128,3) void pass1_hmma()
{
    extern __shared__ uint8_t dyn1[];
    uint8_t* A = (uint8_t*)(((uintptr_t)dyn1 + 1023) & ~(uintptr_t)1023);
    const uint32_t Au = smem_u32(A);
    const uint32_t FQ=0, GB=8192, SG=40960;

    const int t = threadIdx.x, lane = t&31, wid = t>>5;
    const int b = blockIdx.y, i0 = blockIdx.x*64;

    {   // F tile [64 i][64 c]
        const char* fq = (const char*)(g_fq + ((size_t)b*NPIX+i0)*CH);
        for (int q = t; q < 512; q += 128) CP16(Au+FQ+swz(q*16), fq + q*16);
        CPCOMMIT();
    }
#pragma unroll 1
    for (int pre = 0; pre < 2; pre++) {   // G tiles [128 j][64 c]
        const char* gq = (const char*)(g_gq + ((size_t)b*NPIX + pre*128)*CH);
        uint32_t base = Au + GB + pre*16384;
        for (int q = t; q < 1024; q += 128) CP16(base+swz(q*16), gq + q*16);
        CPCOMMIT();
    }
    CPWAIT(2); __syncthreads();   // F ready

    uint32_t af[4][4];
#pragma unroll
    for (int kk = 0; kk < 4; kk++) {
        uint32_t off = swz((uint32_t)((wid*16 + (lane&15))*128 + kk*32 + ((lane>>4)&1)*16));
        ldsm4(af[kk], Au+FQ+off);
    }

    float z0 = 0.f, z1 = 0.f;
    const int r0 = wid*16 + (lane>>2), r1 = r0 + 8;

#pragma unroll 1
    for (int jt = 0; jt < 32; jt++) {
        CPWAIT(1); __syncthreads();
        uint32_t gb = Au + GB + (uint32_t)(jt&1)*16384;

        uint32_t sacc[16][2];
#pragma unroll
        for (int nb = 0; nb < 16; nb++) { sacc[nb][0]=0u; sacc[nb][1]=0u; }

#pragma unroll
        for (int kk = 0; kk < 4; kk++) {
#pragma unroll
            for (int p = 0; p < 8; p++) {
                uint32_t off = swz((uint32_t)((p*16 + ((lane>>4)&1)*8 + (lane&7))*128
                                              + kk*32 + ((lane>>3)&1)*16));
                uint32_t bh[4];
                ldsm4(bh, gb+off);
                mma_h16(sacc[2*p],   af[kk], &bh[0]);
                mma_h16(sacc[2*p+1], af[kk], &bh[2]);
            }
        }
        // Z accumulation (f32 exp, same j order as before)
#pragma unroll
        for (int nb = 0; nb < 16; nb++) {
            float2 a = h2f2(sacc[nb][0]);
            float2 c = h2f2(sacc[nb][1]);
            z0 += ex2(a.x) + ex2(a.y);
            z1 += ex2(c.x) + ex2(c.y);
        }
        // stage s~ tile [64 i][128 j] fp16, xor-swizzled 256B rows
#pragma unroll
        for (int nb = 0; nb < 16; nb++) {
            uint32_t cb = (uint32_t)((nb*8 + (lane&3)*2)*2);
            *(uint32_t*)(A + SG + r0*256 + (cb ^ (uint32_t)((r0&7)<<4))) = sacc[nb][0];
            *(uint32_t*)(A + SG + r1*256 + (cb ^ (uint32_t)((r1&7)<<4))) = sacc[nb][1];
        }
        __syncthreads();
        // coalesced store to g_S
        for (int q = t; q < 1024; q += 128) {
            int row = q>>4, jb = q&15;
            int4 v = *(int4*)(A + SG + row*256 + (((uint32_t)(jb*16)) ^ (uint32_t)((row&7)<<4)));
            *(int4*)(g_S + ((size_t)b*NPIX + i0 + row)*NPIX + jt*128 + jb*8) = v;
        }

        if (jt+2 < 32) {
            const char* gq = (const char*)(g_gq + ((size_t)b*NPIX + (jt+2)*128)*CH);
            uint32_t base = Au + GB + (uint32_t)(jt&1)*16384;
            for (int q = t; q < 1024; q += 128) CP16(base+swz(q*16), gq + q*16);
        }
        CPCOMMIT();
    }

    z0 += __shfl_xor_sync(0xFFFFFFFFu, z0, 1);
    z0 += __shfl_xor_sync(0xFFFFFFFFu, z0, 2);
    z1 += __shfl_xor_sync(0xFFFFFFFFu, z1, 1);
    z1 += __shfl_xor_sync(0xFFFFFFFFu, z1, 2);
    if ((lane&3) == 0) {
        int r = b*NPIX + i0 + wid*16 + (lane>>2);
        g_L[r]   = lg2(z0);
        g_L[r+8] = lg2(z1);
    }
}

// ---------------- Pass 2: out'[j,c]; GEMM2 only, P from stored s~ ------------
// grid (64, 8), 64 threads. smem: 2 x (S' 8K + h 8K + L 256B) = 33K.
#define BUFST 16640u
#define OF_SQ 0u
#define OF_HH 8192u
#define OF_L  16384u
__global__ __launch_bounds__(64,6) void pass2_hmma(
    const float* __restrict__ x, const float* __restrict__ gamma,
    float* __restrict__ out)
{
    extern __shared__ uint8_t dyn2[];
    uint8_t* A = (uint8_t*)(((uintptr_t)dyn2 + 1023) & ~(uintptr_t)1023);
    const uint32_t Au = smem_u32(A);

    const int t = threadIdx.x, lane = t&31, wid = t>>5;
    const int b = blockIdx.y, j0 = blockIdx.x*64;

#pragma unroll 1
    for (int pre = 0; pre < 2; pre++) {
        const int i0 = pre*64;
        uint32_t base = Au + pre*BUFST;
        for (int q = t; q < 512; q += 64)
            CP16(base+OF_SQ+swz(q*16),
                 (const char*)(g_S + ((size_t)b*NPIX + i0 + (q>>3))*NPIX + j0 + (q&7)*8));
        const char* hq = (const char*)(g_hq + (size_t)b*CH*NPIX + i0);
        for (int q = t; q < 512; q += 64)
            CP16(base+OF_HH+swz(q*16), hq + (uint32_t)(q>>3)*NPIX*2 + (uint32_t)(q&7)*16);
        if (t < 16) CP16(base+OF_L + t*16, (const char*)(g_L + b*NPIX + i0) + t*16);
        CPCOMMIT();
    }

    float oacc[2][8][4];
#pragma unroll
    for (int s = 0; s < 2; s++)
#pragma unroll
    for (int nb = 0; nb < 8; nb++) { oacc[s][nb][0]=0.f; oacc[s][nb][1]=0.f; oacc[s][nb][2]=0.f; oacc[s][nb][3]=0.f; }

#pragma unroll 1
    for (int it = 0; it < 64; it++) {
        CPWAIT(1); __syncthreads();
        uint32_t bb = Au + (uint32_t)(it&1)*BUFST;
        const float* Lf = (const float*)(A + (it&1)*BUFST + OF_L);

        uint32_t L2[8];
#pragma unroll
        for (int nb = 0; nb < 8; nb++) {
            int ic = nb*8 + (lane&3)*2;
            L2[nb] = cvtpack(Lf[ic], Lf[ic+1]);
        }

#pragma unroll
        for (int kk2 = 0; kk2 < 4; kk2++) {
            int row = kk2*16 + (lane&7) + ((lane>>4)<<3);
            int colb = ((lane>>3)&1)*8;
            uint32_t r0[4], r1[4];
            ldsm4t(r0, bb + OF_SQ + swz((uint32_t)(row*128 + (wid*32 + colb)*2)));
            ldsm4t(r1, bb + OF_SQ + swz((uint32_t)(row*128 + (wid*32 + 16 + colb)*2)));
            uint32_t aH0[4], aH1[4];
            aH0[0] = ex2h2(sub2(r0[0], L2[2*kk2]));
            aH0[1] = ex2h2(sub2(r0[1], L2[2*kk2]));
            aH0[2] = ex2h2(sub2(r0[2], L2[2*kk2+1]));
            aH0[3] = ex2h2(sub2(r0[3], L2[2*kk2+1]));
            aH1[0] = ex2h2(sub2(r1[0], L2[2*kk2]));
            aH1[1] = ex2h2(sub2(r1[1], L2[2*kk2]));
            aH1[2] = ex2h2(sub2(r1[2], L2[2*kk2+1]));
            aH1[3] = ex2h2(sub2(r1[3], L2[2*kk2+1]));
#pragma unroll
            for (int p = 0; p < 4; p++) {
                uint32_t off = swz((uint32_t)((p*16 + ((lane>>4)&1)*8 + (lane&7))*128
                                              + kk2*32 + ((lane>>3)&1)*16));
                uint32_t bh[4];
                ldsm4(bh, bb+OF_HH+off);
                mma_f16(oacc[0][2*p],   aH0, &bh[0]);
                mma_f16(oacc[0][2*p+1], aH0, &bh[2]);
                mma_f16(oacc[1][2*p],   aH1, &bh[0]);
                mma_f16(oacc[1][2*p+1], aH1, &bh[2]);
            }
        }

        __syncthreads();
        if (it+2 < 64) {
            const int i0 = (it+2)*64;
            uint32_t base = Au + (uint32_t)(it&1)*BUFST;
            for (int q = t; q < 512; q += 64)
                CP16(base+OF_SQ+swz(q*16),
                     (const char*)(g_S + ((size_t)b*NPIX + i0 + (q>>3))*NPIX + j0 + (q&7)*8));
            const char* hq = (const char*)(g_hq + (size_t)b*CH*NPIX + i0);
            for (int q = t; q < 512; q += 64)
                CP16(base+OF_HH+swz(q*16), hq + (uint32_t)(q>>3)*NPIX*2 + (uint32_t)(q&7)*16);
            if (t < 16) CP16(base+OF_L + t*16, (const char*)(g_L + b*NPIX + i0) + t*16);
        }
        CPCOMMIT();
    }

    // Epilogue
    CPWAIT(0); __syncthreads();
    float* outs = (float*)A;
#pragma unroll
    for (int s = 0; s < 2; s++) {
        const int jl = wid*32 + s*16 + (lane>>2);
#pragma unroll
        for (int nb = 0; nb < 8; nb++) {
            int c0 = nb*8 + (lane&3)*2;
            outs[c0*64 + jl]         = oacc[s][nb][0];
            outs[(c0+1)*64 + jl]     = oacc[s][nb][1];
            outs[c0*64 + jl + 8]     = oacc[s][nb][2];
            outs[(c0+1)*64 + jl + 8] = oacc[s][nb][3];
        }
    }
    __syncthreads();
    const float gam = *gamma;
    {
        const int row = t;
        const float* xr   = x   + ((size_t)b*CH + row)*NPIX + j0;
        float*       orow = out + ((size_t)b*CH + row)*NPIX + j0;
        const float4* sr = (const float4*)(outs + row*64);
#pragma unroll
        for (int u = 0; u < 16; u++) {
            float4 v = sr[u];
            float4 xv = *(const float4*)(xr + u*4);
            float4 r;
            r.x = gam*v.x + xv.x; r.y = gam*v.y + xv.y;
            r.z = gam*v.z + xv.z; r.w = gam*v.w + xv.w;
            *(float4*)(orow + u*4) = r;
        }
    }
}

// -----------------------------------------------------------------------------
extern "C" void kernel_launch(void* const* d_in, const int* in_sizes, int n_in,
                              void* d_out, int out_size)
{
    const float* x     = (const float*)d_in[0];
    const float* Wf    = (const float*)d_in[1];
    const float* bf    = (const float*)d_in[2];
    const float* Wg    = (const float*)d_in[3];
    const float* bg    = (const float*)d_in[4];
    const float* Wh    = (const float*)d_in[5];
    const float* bh    = (const float*)d_in[6];
    const float* gamma = (const float*)d_in[7];
    float* out = (float*)d_out;
    (void)in_sizes; (void)n_in; (void)out_size;

    cudaFuncSetAttribute(fgh_hmma,   cudaFuncAttributeMaxDynamicSharedMemorySize, 41984+1024);
    cudaFuncSetAttribute(pass1_hmma, cudaFuncAttributeMaxDynamicSharedMemorySize, 57344+1024);
    cudaFuncSetAttribute(pass2_hmma, cudaFuncAttributeMaxDynamicSharedMemorySize, 33280+1024);

    prep_w<<<1, 256>>>(Wf, bf, Wg, bg, Wh, bh);
    fgh_hmma<<<dim3(64, BATCH), 128, 41984+1024>>>(x);
    pass1_hmma<<<dim3(64, BATCH), 128, 57344+1024>>>();
    pass2_hmma<<<dim3(64, BATCH), 64, 33280+1024>>>(x, gamma, out);
}

// round 16
// speedup vs baseline: 1.1763x; 1.1763x over previous
#include <cuda_runtime.h>
#include <cuda_fp16.h>
#include <cstdint>

#define BATCH 8
#define CH    64
#define NPIX  4096

__device__ __align__(128) __half g_fq[BATCH*NPIX*CH]; // f*log2e [b][n][c]
__device__ __align__(128) __half g_gq[BATCH*NPIX*CH]; // g       [b][n][c]
__device__ __align__(128) __half g_hq[BATCH*CH*NPIX]; // h       [b][c][n]
__device__ float g_zp[2*BATCH*NPIX];                  // Z partials (split-K)
__device__ float g_L[BATCH*NPIX];
__device__ __align__(128) float g_part[(size_t)2*BATCH*64*64*64]; // [kv][b][jt][c][jl]
__device__ __align__(128) uint8_t g_Wq[24576];
__device__ __align__(128) float   g_bias[192];

__device__ __forceinline__ uint32_t smem_u32(const void* p){
    uint32_t a; asm("{ .reg .u64 t; cvta.to.shared.u64 t, %1; cvt.u32.u64 %0, t; }":"=r"(a):"l"(p)); return a;
}
__device__ __forceinline__ uint32_t swz(uint32_t o){ return o ^ ((o>>3)&0x70); }
__device__ __forceinline__ float ex2(float x){
    float y; asm("ex2.approx.f32 %0, %1;":"=f"(y):"f"(x)); return y;
}
__device__ __forceinline__ float lg2(float x){
    float y; asm("lg2.approx.f32 %0, %1;":"=f"(y):"f"(x)); return y;
}
__device__ __forceinline__ uint32_t cvtpack(float lo, float hi){
    uint32_t r; asm("cvt.rn.f16x2.f32 %0, %1, %2;" : "=r"(r) : "f"(hi), "f"(lo)); return r;
}
__device__ __forceinline__ uint32_t sub2(uint32_t a, uint32_t b){
    uint32_t r; asm("sub.rn.f16x2 %0, %1, %2;" : "=r"(r) : "r"(a), "r"(b)); return r;
}
__device__ __forceinline__ uint32_t ex2h2(uint32_t a){
    uint32_t r; asm("ex2.approx.f16x2 %0, %1;" : "=r"(r) : "r"(a)); return r;
}
__device__ __forceinline__ float2 h2f2(uint32_t h){
    return __half22float2(*reinterpret_cast<const __half2*>(&h));
}
#define CP16(dst, src) asm volatile("cp.async.cg.shared.global [%0], [%1], 16;"::"r"(dst),"l"(src):"memory")
#define CPCOMMIT()     asm volatile("cp.async.commit_group;":::"memory")
#define CPWAIT(n)      asm volatile("cp.async.wait_group %0;"::"n"(n):"memory")

__device__ __forceinline__ void ldsm4(uint32_t r[4], uint32_t addr){
    asm volatile("ldmatrix.sync.aligned.m8n8.x4.shared.b16 {%0,%1,%2,%3},[%4];"
        : "=r"(r[0]),"=r"(r[1]),"=r"(r[2]),"=r"(r[3]) : "r"(addr));
}
__device__ __forceinline__ void ldsm4t(uint32_t r[4], uint32_t addr){
    asm volatile("ldmatrix.sync.aligned.m8n8.x4.trans.shared.b16 {%0,%1,%2,%3},[%4];"
        : "=r"(r[0]),"=r"(r[1]),"=r"(r[2]),"=r"(r[3]) : "r"(addr));
}
__device__ __forceinline__ void mma_f16(float d[4], const uint32_t a[4], const uint32_t b[2]){
    asm volatile("mma.sync.aligned.m16n8k16.row.col.f32.f16.f16.f32 "
        "{%0,%1,%2,%3},{%4,%5,%6,%7},{%8,%9},{%0,%1,%2,%3};"
        : "+f"(d[0]),"+f"(d[1]),"+f"(d[2]),"+f"(d[3])
        : "r"(a[0]),"r"(a[1]),"r"(a[2]),"r"(a[3]),"r"(b[0]),"r"(b[1]));
}
__device__ __forceinline__ void mma_h16(uint32_t d[2], const uint32_t a[4], const uint32_t b[2]){
    asm volatile("mma.sync.aligned.m16n8k16.row.col.f16.f16.f16.f16 "
        "{%0,%1},{%2,%3,%4,%5},{%6,%7},{%0,%1};"
        : "+r"(d[0]),"+r"(d[1])
        : "r"(a[0]),"r"(a[1]),"r"(a[2]),"r"(a[3]),"r"(b[0]),"r"(b[1]));
}

// ---------------- Stage 0: W/bias prep ---------------------------------------
__global__ __launch_bounds__(256) void prep_w(
    const float* __restrict__ Wf, const float* __restrict__ bf,
    const float* __restrict__ Wg, const float* __restrict__ bg,
    const float* __restrict__ Wh, const float* __restrict__ bh)
{
    const int t = threadIdx.x;
    for (int q = t; q < 3*4096; q += 256) {
        int mtx = q >> 12, idx = q & 4095;
        const float* Wsrc = (mtx==0)?Wf:((mtx==1)?Wg:Wh);
        float v = Wsrc[idx] * ((mtx==0) ? 1.44269504f : 1.0f);
        int o = idx >> 6, k = idx & 63;
        *(__half*)(g_Wq + mtx*8192u + swz(o*128 + k*2)) = __float2half_rn(v);
    }
    if (t < 192) {
        const float* bsrc = (t<64)?bf:((t<128)?bg:bh);
        g_bias[t] = bsrc[t&63] * ((t<64) ? 1.44269504f : 1.0f);
    }
}

// ---------------- Stage A: projections via HMMA; n-tile 64, 128 thr ----------
__global__ __launch_bounds__(128,4) void fgh_hmma(const float* __restrict__ x)
{
    extern __shared__ uint8_t dyn0[];
    uint8_t* A = (uint8_t*)(((uintptr_t)dyn0 + 1023) & ~(uintptr_t)1023);
    const uint32_t Au = smem_u32(A);
    const uint32_t BIAS=24576, SX=25600, STG=33792;

    const int t = threadIdx.x, lane = t&31, wid = t>>5;
    const int b = blockIdx.y, n0 = blockIdx.x*64;

    for (int q = t; q < 1536; q += 128) CP16(Au + q*16, (const char*)g_Wq + q*16);
    if (t < 48) CP16(Au + BIAS + t*16, (const char*)g_bias + t*16);
    CPCOMMIT();

    {
        int c = t>>1, half = t&1;
        const float* xr = x + ((size_t)b*CH + c)*NPIX + n0 + half*32;
#pragma unroll
        for (int u = 0; u < 16; u++) {
            float2 v = *(const float2*)(xr + 2*u);
            *(uint32_t*)(A + SX + swz((uint32_t)(c*128 + (half*32 + 2*u)*2))) = cvtpack(v.x, v.y);
        }
    }
    CPWAIT(0); __syncthreads();

    uint32_t ax[4][4];
    const int m0 = wid*16;
#pragma unroll
    for (int kk = 0; kk < 4; kk++) {
        int row = kk*16 + (lane&7) + ((lane>>4)<<3);
        int col = m0 + ((lane>>3)&1)*8;
        ldsm4t(ax[kk], Au + SX + swz((uint32_t)(row*128 + col*2)));
    }
    const float* bias = (const float*)(A+BIAS);

#pragma unroll 1
    for (int mtx = 0; mtx < 3; mtx++) {
        float acc[8][4];
#pragma unroll
        for (int ob = 0; ob < 8; ob++) {
            float b0 = bias[mtx*64 + ob*8 + (lane&3)*2];
            float b1 = bias[mtx*64 + ob*8 + (lane&3)*2 + 1];
            acc[ob][0]=b0; acc[ob][1]=b1; acc[ob][2]=b0; acc[ob][3]=b1;
        }
#pragma unroll
        for (int kk = 0; kk < 4; kk++) {
#pragma unroll
            for (int op = 0; op < 4; op++) {
                uint32_t off = swz((uint32_t)((op*16 + ((lane>>4)&1)*8 + (lane&7))*128
                                              + kk*32 + ((lane>>3)&1)*16));
                uint32_t bw[4];
                ldsm4(bw, Au + mtx*8192u + off);
                mma_f16(acc[2*op],   ax[kk], &bw[0]);
                mma_f16(acc[2*op+1], ax[kk], &bw[2]);
            }
        }
        __syncthreads();
#pragma unroll
        for (int ob = 0; ob < 8; ob++) {
            int o = ob*8 + (lane&3)*2, r = lane>>2;
            *(uint32_t*)(A + STG + swz((uint32_t)((m0+r)*128   + o*2))) = cvtpack(acc[ob][0], acc[ob][1]);
            *(uint32_t*)(A + STG + swz((uint32_t)((m0+r+8)*128 + o*2))) = cvtpack(acc[ob][2], acc[ob][3]);
        }
        __syncthreads();
        if (mtx < 2) {
            char* dst = (char*)(((mtx==0)?g_fq:g_gq) + ((size_t)b*NPIX + n0)*CH);
#pragma unroll
            for (int q = t; q < 512; q += 128) {
                int4 v = *(int4*)(A + STG + swz((uint32_t)(q*16)));
                *(int4*)(dst + q*16) = v;
            }
        } else {
            int c = t>>1, half = t&1;
            __half* dst = g_hq + ((size_t)b*CH + c)*NPIX + n0;
#pragma unroll
            for (int u = 0; u < 16; u++) {
                int n = half*32 + 2*u;
                uint32_t e0 = *(uint16_t*)(A + STG + swz((uint32_t)(n*128 + c*2)));
                uint32_t e1 = *(uint16_t*)(A + STG + swz((uint32_t)((n+1)*128 + c*2)));
                *(uint32_t*)(dst + n) = e0 | (e1<<16);
            }
        }
    }
}

// ---------------- Pass 1: Z partials; split-K over j (kv = blockIdx.z) -------
// grid (64, 8, 2), 64 threads. smem: F 8K | G dbl 2x16K = 40K.
__global__ __launch_bounds__(64,5) void pass1_hmma()
{
    extern __shared__ uint8_t dyn1[];
    uint8_t* A = (uint8_t*)(((uintptr_t)dyn1 + 1023) & ~(uintptr_t)1023);
    const uint32_t Au = smem_u32(A);
    const uint32_t FQ=0, GB=8192;

    const int t = threadIdx.x, lane = t&31, wid = t>>5;
    const int b = blockIdx.y, i0 = blockIdx.x*64;
    const int kv = blockIdx.z;
    const int jt0 = kv*16, jt1 = jt0 + 16;   // 16 j-tiles of 128 each

    {
        const char* fq = (const char*)(g_fq + ((size_t)b*NPIX+i0)*CH);
        for (int q = t; q < 512; q += 64) CP16(Au+FQ+swz(q*16), fq + q*16);
        CPCOMMIT();
    }
#pragma unroll 1
    for (int pre = 0; pre < 2; pre++) {
        const char* gq = (const char*)(g_gq + ((size_t)b*NPIX + (jt0+pre)*128)*CH);
        uint32_t base = Au + GB + pre*16384;
        for (int q = t; q < 1024; q += 64) CP16(base+swz(q*16), gq + q*16);
        CPCOMMIT();
    }
    CPWAIT(2); __syncthreads();

    uint32_t af[2][4][4];
#pragma unroll
    for (int s = 0; s < 2; s++)
#pragma unroll
    for (int kk = 0; kk < 4; kk++) {
        uint32_t off = swz((uint32_t)((wid*32 + s*16 + (lane&15))*128 + kk*32 + ((lane>>4)&1)*16));
        ldsm4(af[s][kk], Au+FQ+off);
    }

    float z[2][2] = {{0.f,0.f},{0.f,0.f}};

#pragma unroll 1
    for (int jt = jt0; jt < jt1; jt++) {
        CPWAIT(1); __syncthreads();
        uint32_t gb = Au + GB + (uint32_t)(jt&1)*16384;

        uint32_t sacc[2][16][2];
#pragma unroll
        for (int s = 0; s < 2; s++)
#pragma unroll
        for (int nb = 0; nb < 16; nb++) { sacc[s][nb][0]=0u; sacc[s][nb][1]=0u; }

#pragma unroll
        for (int kk = 0; kk < 4; kk++) {
#pragma unroll
            for (int p = 0; p < 8; p++) {
                uint32_t off = swz((uint32_t)((p*16 + ((lane>>4)&1)*8 + (lane&7))*128
                                              + kk*32 + ((lane>>3)&1)*16));
                uint32_t bh[4];
                ldsm4(bh, gb+off);
                mma_h16(sacc[0][2*p],   af[0][kk], &bh[0]);
                mma_h16(sacc[0][2*p+1], af[0][kk], &bh[2]);
                mma_h16(sacc[1][2*p],   af[1][kk], &bh[0]);
                mma_h16(sacc[1][2*p+1], af[1][kk], &bh[2]);
            }
        }
#pragma unroll
        for (int s = 0; s < 2; s++)
#pragma unroll
        for (int nb = 0; nb < 16; nb++) {
            float2 a = h2f2(sacc[s][nb][0]);
            float2 c = h2f2(sacc[s][nb][1]);
            z[s][0] += ex2(a.x) + ex2(a.y);
            z[s][1] += ex2(c.x) + ex2(c.y);
        }

        __syncthreads();
        if (jt+2 < jt1) {
            const char* gq = (const char*)(g_gq + ((size_t)b*NPIX + (jt+2)*128)*CH);
            uint32_t base = Au + GB + (uint32_t)(jt&1)*16384;
            for (int q = t; q < 1024; q += 64) CP16(base+swz(q*16), gq + q*16);
        }
        CPCOMMIT();
    }

#pragma unroll
    for (int s = 0; s < 2; s++) {
        float z0 = z[s][0], z1 = z[s][1];
        z0 += __shfl_xor_sync(0xFFFFFFFFu, z0, 1);
        z0 += __shfl_xor_sync(0xFFFFFFFFu, z0, 2);
        z1 += __shfl_xor_sync(0xFFFFFFFFu, z1, 1);
        z1 += __shfl_xor_sync(0xFFFFFFFFu, z1, 2);
        if ((lane&3) == 0) {
            int r = kv*BATCH*NPIX + b*NPIX + i0 + wid*32 + s*16 + (lane>>2);
            g_zp[r]   = z0;
            g_zp[r+8] = z1;
        }
    }
}

// ---------------- combine: L = lg2(z0 + z1) ----------------------------------
__global__ __launch_bounds__(256) void combine_L()
{
    int idx = blockIdx.x*256 + threadIdx.x;
    g_L[idx] = lg2(g_zp[idx] + g_zp[BATCH*NPIX + idx]);
}

// ---------------- Pass 2: partial out'[j,c]; split-K over i ------------------
// grid (64, 8, 2), 64 threads. smem: G 8K + 2 x 16.25K = 41.5K.
#define BUFST 16640u
#define B0    8192u
#define OF_FQ 0u
#define OF_HH 8192u
#define OF_L  16384u
__global__ __launch_bounds__(64,5) void pass2_hmma()
{
    extern __shared__ uint8_t dyn2[];
    uint8_t* A = (uint8_t*)(((uintptr_t)dyn2 + 1023) & ~(uintptr_t)1023);
    const uint32_t Au = smem_u32(A);

    const int t = threadIdx.x, lane = t&31, wid = t>>5;
    const int b = blockIdx.y, j0 = blockIdx.x*64;
    const int kv = blockIdx.z;
    const int it0 = kv*32, it1 = it0 + 32;

    {
        const char* gq = (const char*)(g_gq + ((size_t)b*NPIX+j0)*CH);
        for (int q = t; q < 512; q += 64) CP16(Au+swz(q*16), gq + q*16);
        CPCOMMIT();
    }
#pragma unroll 1
    for (int pre = 0; pre < 2; pre++) {
        const int i0 = (it0 + pre)*64;
        uint32_t base = Au + B0 + pre*BUFST;
        const char* fq = (const char*)(g_fq + ((size_t)b*NPIX+i0)*CH);
        for (int q = t; q < 512; q += 64) CP16(base+OF_FQ+swz(q*16), fq + q*16);
        const char* hq = (const char*)(g_hq + (size_t)b*CH*NPIX + i0);
        for (int q = t; q < 512; q += 64)
            CP16(base+OF_HH+swz(q*16), hq + (uint32_t)(q>>3)*NPIX*2 + (uint32_t)(q&7)*16);
        if (t < 16) CP16(base+OF_L + t*16, (const char*)(g_L + b*NPIX + i0) + t*16);
        CPCOMMIT();
    }
    CPWAIT(2); __syncthreads();

    uint32_t ag[2][4][4];
#pragma unroll
    for (int s = 0; s < 2; s++)
#pragma unroll
    for (int kk = 0; kk < 4; kk++) {
        uint32_t off = swz((uint32_t)((wid*32 + s*16 + (lane&15))*128 + kk*32 + ((lane>>4)&1)*16));
        ldsm4(ag[s][kk], Au+off);
    }

    float oacc[2][8][4];
#pragma unroll
    for (int s = 0; s < 2; s++)
#pragma unroll
    for (int nb = 0; nb < 8; nb++) { oacc[s][nb][0]=0.f; oacc[s][nb][1]=0.f; oacc[s][nb][2]=0.f; oacc[s][nb][3]=0.f; }

#pragma unroll 1
    for (int it = it0; it < it1; it++) {
        CPWAIT(1); __syncthreads();
        uint32_t bb = Au + B0 + (uint32_t)(it&1)*BUFST;
        const float* Lf = (const float*)(A + B0 + (it&1)*BUFST + OF_L);

        uint32_t L2[8];
#pragma unroll
        for (int nb = 0; nb < 8; nb++) {
            int ic = nb*8 + (lane&3)*2;
            L2[nb] = cvtpack(Lf[ic], Lf[ic+1]);
        }

        uint32_t sacc[2][8][2];
#pragma unroll
        for (int s = 0; s < 2; s++)
#pragma unroll
        for (int nb = 0; nb < 8; nb++) { sacc[s][nb][0]=0u; sacc[s][nb][1]=0u; }
#pragma unroll
        for (int kk = 0; kk < 4; kk++) {
#pragma unroll
            for (int p = 0; p < 4; p++) {
                uint32_t off = swz((uint32_t)((p*16 + ((lane>>4)&1)*8 + (lane&7))*128
                                              + kk*32 + ((lane>>3)&1)*16));
                uint32_t bh[4];
                ldsm4(bh, bb+OF_FQ+off);
                mma_h16(sacc[0][2*p],   ag[0][kk], &bh[0]);
                mma_h16(sacc[0][2*p+1], ag[0][kk], &bh[2]);
                mma_h16(sacc[1][2*p],   ag[1][kk], &bh[0]);
                mma_h16(sacc[1][2*p+1], ag[1][kk], &bh[2]);
            }
        }

#pragma unroll
        for (int kk2 = 0; kk2 < 4; kk2++) {
            int nb0 = 2*kk2, nb1 = nb0+1;
            uint32_t aH0[4], aH1[4];
            aH0[0] = ex2h2(sub2(sacc[0][nb0][0], L2[nb0]));
            aH0[1] = ex2h2(sub2(sacc[0][nb0][1], L2[nb0]));
            aH0[2] = ex2h2(sub2(sacc[0][nb1][0], L2[nb1]));
            aH0[3] = ex2h2(sub2(sacc[0][nb1][1], L2[nb1]));
            aH1[0] = ex2h2(sub2(sacc[1][nb0][0], L2[nb0]));
            aH1[1] = ex2h2(sub2(sacc[1][nb0][1], L2[nb0]));
            aH1[2] = ex2h2(sub2(sacc[1][nb1][0], L2[nb1]));
            aH1[3] = ex2h2(sub2(sacc[1][nb1][1], L2[nb1]));
#pragma unroll
            for (int p = 0; p < 4; p++) {
                uint32_t off = swz((uint32_t)((p*16 + ((lane>>4)&1)*8 + (lane&7))*128
                                              + kk2*32 + ((lane>>3)&1)*16));
                uint32_t bh[4];
                ldsm4(bh, bb+OF_HH+off);
                mma_f16(oacc[0][2*p],   aH0, &bh[0]);
                mma_f16(oacc[0][2*p+1], aH0, &bh[2]);
                mma_f16(oacc[1][2*p],   aH1, &bh[0]);
                mma_f16(oacc[1][2*p+1], aH1, &bh[2]);
            }
        }

        __syncthreads();
        if (it+2 < it1) {
            const int i0 = (it+2)*64;
            uint32_t base = Au + B0 + (uint32_t)(it&1)*BUFST;
            const char* fq = (const char*)(g_fq + ((size_t)b*NPIX+i0)*CH);
            for (int q = t; q < 512; q += 64) CP16(base+OF_FQ+swz(q*16), fq + q*16);
            const char* hq = (const char*)(g_hq + (size_t)b*CH*NPIX + i0);
            for (int q = t; q < 512; q += 64)
                CP16(base+OF_HH+swz(q*16), hq + (uint32_t)(q>>3)*NPIX*2 + (uint32_t)(q&7)*16);
            if (t < 16) CP16(base+OF_L + t*16, (const char*)(g_L + b*NPIX + i0) + t*16);
        }
        CPCOMMIT();
    }

    // stage [64 c][64 j] fp32 in smem, then bulk-store partial
    CPWAIT(0); __syncthreads();
    float* outs = (float*)A;
#pragma unroll
    for (int s = 0; s < 2; s++) {
        const int jl = wid*32 + s*16 + (lane>>2);
#pragma unroll
        for (int nb = 0; nb < 8; nb++) {
            int c0 = nb*8 + (lane&3)*2;
            outs[c0*64 + jl]         = oacc[s][nb][0];
            outs[(c0+1)*64 + jl]     = oacc[s][nb][1];
            outs[c0*64 + jl + 8]     = oacc[s][nb][2];
            outs[(c0+1)*64 + jl + 8] = oacc[s][nb][3];
        }
    }
    __syncthreads();
    {
        float* pp = g_part + (((size_t)kv*BATCH + b)*64 + blockIdx.x)*4096;
        const float4* sp = (const float4*)outs;
        float4* dp = (float4*)pp;
        for (int q = t; q < 1024; q += 64) dp[q] = sp[q];
    }
}

// ---------------- Final epilogue: out = gamma*(p0+p1) + x --------------------
__global__ __launch_bounds__(256) void final_epi(
    const float* __restrict__ x, const float* __restrict__ gamma,
    float* __restrict__ out)
{
    const int t = threadIdx.x;
    const int b = blockIdx.y, jt = blockIdx.x;
    const float gam = *gamma;
    const float* p0 = g_part + (((size_t)0*BATCH + b)*64 + jt)*4096;
    const float* p1 = g_part + (((size_t)1*BATCH + b)*64 + jt)*4096;
    const int c = t>>2, seg = t&3;
    const int off = c*64 + seg*16;
    const float* xr   = x   + ((size_t)b*CH + c)*NPIX + jt*64 + seg*16;
    float*       orow = out + ((size_t)b*CH + c)*NPIX + jt*64 + seg*16;
#pragma unroll
    for (int u = 0; u < 4; u++) {
        float4 a = *(const float4*)(p0 + off + u*4);
        float4 bvec = *(const float4*)(p1 + off + u*4);
        float4 xv = *(const float4*)(xr + u*4);
        float4 r;
        r.x = gam*(a.x+bvec.x) + xv.x;
        r.y = gam*(a.y+bvec.y) + xv.y;
        r.z = gam*(a.z+bvec.z) + xv.z;
        r.w = gam*(a.w+bvec.w) + xv.w;
        *(float4*)(orow + u*4) = r;
    }
}

// -----------------------------------------------------------------------------
extern "C" void kernel_launch(void* const* d_in, const int* in_sizes, int n_in,
                              void* d_out, int out_size)
{
    const float* x     = (const float*)d_in[0];
    const float* Wf    = (const float*)d_in[1];
    const float* bf    = (const float*)d_in[2];
    const float* Wg    = (const float*)d_in[3];
    const float* bg    = (const float*)d_in[4];
    const float* Wh    = (const float*)d_in[5];
    const float* bh    = (const float*)d_in[6];
    const float* gamma = (const float*)d_in[7];
    float* out = (float*)d_out;
    (void)in_sizes; (void)n_in; (void)out_size;

    cudaFuncSetAttribute(fgh_hmma,   cudaFuncAttributeMaxDynamicSharedMemorySize, 41984+1024);
    cudaFuncSetAttribute(pass1_hmma, cudaFuncAttributeMaxDynamicSharedMemorySize, 40960+1024);
    cudaFuncSetAttribute(pass2_hmma, cudaFuncAttributeMaxDynamicSharedMemorySize, 41472+1024);

    prep_w<<<1, 256>>>(Wf, bf, Wg, bg, Wh, bh);
    fgh_hmma<<<dim3(64, BATCH), 128, 41984+1024>>>(x);
    pass1_hmma<<<dim3(64, BATCH, 2), 64, 40960+1024>>>();
    combine_L<<<BATCH*NPIX/256, 256>>>();
    pass2_hmma<<<dim3(64, BATCH, 2), 64, 41472+1024>>>();
    final_epi<<<dim3(64, BATCH), 256>>>(x, gamma, out);
}

// round 17
// speedup vs baseline: 1.2275x; 1.0435x over previous
#include <cuda_runtime.h>
#include <cuda_fp16.h>
#include <cstdint>

#define BATCH 8
#define CH    64
#define NPIX  4096

__device__ __align__(128) __half g_fq[BATCH*NPIX*CH];
__device__ __align__(128) __half g_gq[BATCH*NPIX*CH];
__device__ __align__(128) __half g_hq[BATCH*CH*NPIX];
__device__ float g_zp[2*BATCH*NPIX];
__device__ float g_L[BATCH*NPIX];
__device__ __align__(128) float g_part[(size_t)2*BATCH*64*64*64];
__device__ __align__(128) uint8_t g_Wq[24576];
__device__ __align__(128) float   g_bias[192];

__device__ __forceinline__ uint32_t smem_u32(const void* p){
    uint32_t a; asm("{ .reg .u64 t; cvta.to.shared.u64 t, %1; cvt.u32.u64 %0, t; }":"=r"(a):"l"(p)); return a;
}
__device__ __forceinline__ uint32_t swz(uint32_t o){ return o ^ ((o>>3)&0x70); }
__device__ __forceinline__ float ex2(float x){
    float y; asm("ex2.approx.f32 %0, %1;":"=f"(y):"f"(x)); return y;
}
__device__ __forceinline__ float lg2(float x){
    float y; asm("lg2.approx.f32 %0, %1;":"=f"(y):"f"(x)); return y;
}
__device__ __forceinline__ uint32_t cvtpack(float lo, float hi){
    uint32_t r; asm("cvt.rn.f16x2.f32 %0, %1, %2;" : "=r"(r) : "f"(hi), "f"(lo)); return r;
}
__device__ __forceinline__ uint32_t sub2(uint32_t a, uint32_t b){
    uint32_t r; asm("sub.rn.f16x2 %0, %1, %2;" : "=r"(r) : "r"(a), "r"(b)); return r;
}
__device__ __forceinline__ uint32_t ex2h2(uint32_t a){
    uint32_t r; asm("ex2.approx.f16x2 %0, %1;" : "=r"(r) : "r"(a)); return r;
}
__device__ __forceinline__ float2 h2f2(uint32_t h){
    return __half22float2(*reinterpret_cast<const __half2*>(&h));
}
#define CP16(dst, src) asm volatile("cp.async.cg.shared.global [%0], [%1], 16;"::"r"(dst),"l"(src):"memory")
#define CPCOMMIT()     asm volatile("cp.async.commit_group;":::"memory")
#define CPWAIT(n)      asm volatile("cp.async.wait_group %0;"::"n"(n):"memory")

__device__ __forceinline__ void ldsm4(uint32_t r[4], uint32_t addr){
    asm volatile("ldmatrix.sync.aligned.m8n8.x4.shared.b16 {%0,%1,%2,%3},[%4];"
        : "=r"(r[0]),"=r"(r[1]),"=r"(r[2]),"=r"(r[3]) : "r"(addr));
}
__device__ __forceinline__ void ldsm4t(uint32_t r[4], uint32_t addr){
    asm volatile("ldmatrix.sync.aligned.m8n8.x4.trans.shared.b16 {%0,%1,%2,%3},[%4];"
        : "=r"(r[0]),"=r"(r[1]),"=r"(r[2]),"=r"(r[3]) : "r"(addr));
}
__device__ __forceinline__ void mma_f16(float d[4], const uint32_t a[4], const uint32_t b[2]){
    asm volatile("mma.sync.aligned.m16n8k16.row.col.f32.f16.f16.f32 "
        "{%0,%1,%2,%3},{%4,%5,%6,%7},{%8,%9},{%0,%1,%2,%3};"
        : "+f"(d[0]),"+f"(d[1]),"+f"(d[2]),"+f"(d[3])
        : "r"(a[0]),"r"(a[1]),"r"(a[2]),"r"(a[3]),"r"(b[0]),"r"(b[1]));
}
__device__ __forceinline__ void mma_h16(uint32_t d[2], const uint32_t a[4], const uint32_t b[2]){
    asm volatile("mma.sync.aligned.m16n8k16.row.col.f16.f16.f16.f16 "
        "{%0,%1},{%2,%3,%4,%5},{%6,%7},{%0,%1};"
        : "+r"(d[0]),"+r"(d[1])
        : "r"(a[0]),"r"(a[1]),"r"(a[2]),"r"(a[3]),"r"(b[0]),"r"(b[1]));
}

// ---------------- Stage 0: W/bias prep ---------------------------------------
__global__ __launch_bounds__(256) void prep_w(
    const float* __restrict__ Wf, const float* __restrict__ bf,
    const float* __restrict__ Wg, const float* __restrict__ bg,
    const float* __restrict__ Wh, const float* __restrict__ bh)
{
    const int t = threadIdx.x;
    for (int q = t; q < 3*4096; q += 256) {
        int mtx = q >> 12, idx = q & 4095;
        const float* Wsrc = (mtx==0)?Wf:((mtx==1)?Wg:Wh);
        float v = Wsrc[idx] * ((mtx==0) ? 1.44269504f : 1.0f);
        int o = idx >> 6, k = idx & 63;
        *(__half*)(g_Wq + mtx*8192u + swz(o*128 + k*2)) = __float2half_rn(v);
    }
    if (t < 192) {
        const float* bsrc = (t<64)?bf:((t<128)?bg:bh);
        g_bias[t] = bsrc[t&63] * ((t<64) ? 1.44269504f : 1.0f);
    }
}

// ---------------- Stage A: projections via HMMA ------------------------------
__global__ __launch_bounds__(128,4) void fgh_hmma(const float* __restrict__ x)
{
    extern __shared__ uint8_t dyn0[];
    uint8_t* A = (uint8_t*)(((uintptr_t)dyn0 + 1023) & ~(uintptr_t)1023);
    const uint32_t Au = smem_u32(A);
    const uint32_t BIAS=24576, SX=25600, STG=33792;

    const int t = threadIdx.x, lane = t&31, wid = t>>5;
    const int b = blockIdx.y, n0 = blockIdx.x*64;

    for (int q = t; q < 1536; q += 128) CP16(Au + q*16, (const char*)g_Wq + q*16);
    if (t < 48) CP16(Au + BIAS + t*16, (const char*)g_bias + t*16);
    CPCOMMIT();

    {
        int c = t>>1, half = t&1;
        const float* xr = x + ((size_t)b*CH + c)*NPIX + n0 + half*32;
#pragma unroll
        for (int u = 0; u < 16; u++) {
            float2 v = *(const float2*)(xr + 2*u);
            *(uint32_t*)(A + SX + swz((uint32_t)(c*128 + (half*32 + 2*u)*2))) = cvtpack(v.x, v.y);
        }
    }
    CPWAIT(0); __syncthreads();

    uint32_t ax[4][4];
    const int m0 = wid*16;
#pragma unroll
    for (int kk = 0; kk < 4; kk++) {
        int row = kk*16 + (lane&7) + ((lane>>4)<<3);
        int col = m0 + ((lane>>3)&1)*8;
        ldsm4t(ax[kk], Au + SX + swz((uint32_t)(row*128 + col*2)));
    }
    const float* bias = (const float*)(A+BIAS);

#pragma unroll 1
    for (int mtx = 0; mtx < 3; mtx++) {
        float acc[8][4];
#pragma unroll
        for (int ob = 0; ob < 8; ob++) {
            float b0 = bias[mtx*64 + ob*8 + (lane&3)*2];
            float b1 = bias[mtx*64 + ob*8 + (lane&3)*2 + 1];
            acc[ob][0]=b0; acc[ob][1]=b1; acc[ob][2]=b0; acc[ob][3]=b1;
        }
#pragma unroll
        for (int kk = 0; kk < 4; kk++) {
#pragma unroll
            for (int op = 0; op < 4; op++) {
                uint32_t off = swz((uint32_t)((op*16 + ((lane>>4)&1)*8 + (lane&7))*128
                                              + kk*32 + ((lane>>3)&1)*16));
                uint32_t bw[4];
                ldsm4(bw, Au + mtx*8192u + off);
                mma_f16(acc[2*op],   ax[kk], &bw[0]);
                mma_f16(acc[2*op+1], ax[kk], &bw[2]);
            }
        }
        __syncthreads();
#pragma unroll
        for (int ob = 0; ob < 8; ob++) {
            int o = ob*8 + (lane&3)*2, r = lane>>2;
            *(uint32_t*)(A + STG + swz((uint32_t)((m0+r)*128   + o*2))) = cvtpack(acc[ob][0], acc[ob][1]);
            *(uint32_t*)(A + STG + swz((uint32_t)((m0+r+8)*128 + o*2))) = cvtpack(acc[ob][2], acc[ob][3]);
        }
        __syncthreads();
        if (mtx < 2) {
            char* dst = (char*)(((mtx==0)?g_fq:g_gq) + ((size_t)b*NPIX + n0)*CH);
#pragma unroll
            for (int q = t; q < 512; q += 128) {
                int4 v = *(int4*)(A + STG + swz((uint32_t)(q*16)));
                *(int4*)(dst + q*16) = v;
            }
        } else {
            int c = t>>1, half = t&1;
            __half* dst = g_hq + ((size_t)b*CH + c)*NPIX + n0;
#pragma unroll
            for (int u = 0; u < 16; u++) {
                int n = half*32 + 2*u;
                uint32_t e0 = *(uint16_t*)(A + STG + swz((uint32_t)(n*128 + c*2)));
                uint32_t e1 = *(uint16_t*)(A + STG + swz((uint32_t)((n+1)*128 + c*2)));
                *(uint32_t*)(dst + n) = e0 | (e1<<16);
            }
        }
    }
}

// ---------------- Pass 1: Z partials; split-K j; j-tile 64; smem 24K ---------
__global__ __launch_bounds__(64,7) void pass1_hmma()
{
    extern __shared__ uint8_t dyn1[];
    uint8_t* A = (uint8_t*)(((uintptr_t)dyn1 + 1023) & ~(uintptr_t)1023);
    const uint32_t Au = smem_u32(A);
    const uint32_t FQ=0, GB=8192;   // G dbl buffers 2x8K

    const int t = threadIdx.x, lane = t&31, wid = t>>5;
    const int b = blockIdx.y, i0 = blockIdx.x*64;
    const int kv = blockIdx.z;
    const int jt0 = kv*32, jt1 = jt0 + 32;   // 32 j-tiles of 64

    {
        const char* fq = (const char*)(g_fq + ((size_t)b*NPIX+i0)*CH);
        for (int q = t; q < 512; q += 64) CP16(Au+FQ+swz(q*16), fq + q*16);
        CPCOMMIT();
    }
#pragma unroll 1
    for (int pre = 0; pre < 2; pre++) {
        const char* gq = (const char*)(g_gq + ((size_t)b*NPIX + (jt0+pre)*64)*CH);
        uint32_t base = Au + GB + pre*8192;
        for (int q = t; q < 512; q += 64) CP16(base+swz(q*16), gq + q*16);
        CPCOMMIT();
    }
    CPWAIT(2); __syncthreads();

    uint32_t af[2][4][4];
#pragma unroll
    for (int s = 0; s < 2; s++)
#pragma unroll
    for (int kk = 0; kk < 4; kk++) {
        uint32_t off = swz((uint32_t)((wid*32 + s*16 + (lane&15))*128 + kk*32 + ((lane>>4)&1)*16));
        ldsm4(af[s][kk], Au+FQ+off);
    }

    float z[2][2] = {{0.f,0.f},{0.f,0.f}};

#pragma unroll 1
    for (int jt = jt0; jt < jt1; jt++) {
        CPWAIT(1); __syncthreads();
        uint32_t gb = Au + GB + (uint32_t)(jt&1)*8192;

        uint32_t sacc[2][8][2];
#pragma unroll
        for (int s = 0; s < 2; s++)
#pragma unroll
        for (int nb = 0; nb < 8; nb++) { sacc[s][nb][0]=0u; sacc[s][nb][1]=0u; }

#pragma unroll
        for (int kk = 0; kk < 4; kk++) {
#pragma unroll
            for (int p = 0; p < 4; p++) {
                uint32_t off = swz((uint32_t)((p*16 + ((lane>>4)&1)*8 + (lane&7))*128
                                              + kk*32 + ((lane>>3)&1)*16));
                uint32_t bh[4];
                ldsm4(bh, gb+off);
                mma_h16(sacc[0][2*p],   af[0][kk], &bh[0]);
                mma_h16(sacc[0][2*p+1], af[0][kk], &bh[2]);
                mma_h16(sacc[1][2*p],   af[1][kk], &bh[0]);
                mma_h16(sacc[1][2*p+1], af[1][kk], &bh[2]);
            }
        }
#pragma unroll
        for (int s = 0; s < 2; s++)
#pragma unroll
        for (int nb = 0; nb < 8; nb++) {
            float2 a = h2f2(sacc[s][nb][0]);
            float2 c = h2f2(sacc[s][nb][1]);
            z[s][0] += ex2(a.x) + ex2(a.y);
            z[s][1] += ex2(c.x) + ex2(c.y);
        }

        __syncthreads();
        if (jt+2 < jt1) {
            const char* gq = (const char*)(g_gq + ((size_t)b*NPIX + (jt+2)*64)*CH);
            uint32_t base = Au + GB + (uint32_t)(jt&1)*8192;
            for (int q = t; q < 512; q += 64) CP16(base+swz(q*16), gq + q*16);
        }
        CPCOMMIT();
    }

#pragma unroll
    for (int s = 0; s < 2; s++) {
        float z0 = z[s][0], z1 = z[s][1];
        z0 += __shfl_xor_sync(0xFFFFFFFFu, z0, 1);
        z0 += __shfl_xor_sync(0xFFFFFFFFu, z0, 2);
        z1 += __shfl_xor_sync(0xFFFFFFFFu, z1, 1);
        z1 += __shfl_xor_sync(0xFFFFFFFFu, z1, 2);
        if ((lane&3) == 0) {
            int r = kv*BATCH*NPIX + b*NPIX + i0 + wid*32 + s*16 + (lane>>2);
            g_zp[r]   = z0;
            g_zp[r+8] = z1;
        }
    }
}

// ---------------- combine: L = lg2(z0 + z1) ----------------------------------
__global__ __launch_bounds__(256) void combine_L()
{
    int idx = blockIdx.x*256 + threadIdx.x;
    g_L[idx] = lg2(g_zp[idx] + g_zp[BATCH*NPIX + idx]);
}

// ---------------- Pass 2: split-K i; single buffers, phase-pipelined ---------
// smem: G 8K @0 | f 8K @8192 | h 8K @16384 | L 256B @24576 -> 24.8K
#define OF_FQ 8192u
#define OF_HH 16384u
#define OF_L  24576u
__global__ __launch_bounds__(64,6) void pass2_hmma()
{
    extern __shared__ uint8_t dyn2[];
    uint8_t* A = (uint8_t*)(((uintptr_t)dyn2 + 1023) & ~(uintptr_t)1023);
    const uint32_t Au = smem_u32(A);

    const int t = threadIdx.x, lane = t&31, wid = t>>5;
    const int b = blockIdx.y, j0 = blockIdx.x*64;
    const int kv = blockIdx.z;
    const int it0 = kv*32, it1 = it0 + 32;

    {   // G once
        const char* gq = (const char*)(g_gq + ((size_t)b*NPIX+j0)*CH);
        for (int q = t; q < 512; q += 64) CP16(Au+swz(q*16), gq + q*16);
        CPCOMMIT();
    }
    {   // f(it0) + L(it0)
        const int i0 = it0*64;
        const char* fq = (const char*)(g_fq + ((size_t)b*NPIX+i0)*CH);
        for (int q = t; q < 512; q += 64) CP16(Au+OF_FQ+swz(q*16), fq + q*16);
        if (t < 16) CP16(Au+OF_L + t*16, (const char*)(g_L + b*NPIX + i0) + t*16);
        CPCOMMIT();
    }
    {   // h(it0)
        const int i0 = it0*64;
        const char* hq = (const char*)(g_hq + (size_t)b*CH*NPIX + i0);
        for (int q = t; q < 512; q += 64)
            CP16(Au+OF_HH+swz(q*16), hq + (uint32_t)(q>>3)*NPIX*2 + (uint32_t)(q&7)*16);
        CPCOMMIT();
    }
    CPWAIT(2); __syncthreads();   // G ready

    uint32_t ag[2][4][4];
#pragma unroll
    for (int s = 0; s < 2; s++)
#pragma unroll
    for (int kk = 0; kk < 4; kk++) {
        uint32_t off = swz((uint32_t)((wid*32 + s*16 + (lane&15))*128 + kk*32 + ((lane>>4)&1)*16));
        ldsm4(ag[s][kk], Au+off);
    }

    float oacc[2][8][4];
#pragma unroll
    for (int s = 0; s < 2; s++)
#pragma unroll
    for (int nb = 0; nb < 8; nb++) { oacc[s][nb][0]=0.f; oacc[s][nb][1]=0.f; oacc[s][nb][2]=0.f; oacc[s][nb][3]=0.f; }

#pragma unroll 1
    for (int it = it0; it < it1; it++) {
        CPWAIT(1); __syncthreads();   // f(it)+L(it) ready; h(it) may be in flight
        const float* Lf = (const float*)(A + OF_L);

        uint32_t L2[8];
#pragma unroll
        for (int nb = 0; nb < 8; nb++) {
            int ic = nb*8 + (lane&3)*2;
            L2[nb] = cvtpack(Lf[ic], Lf[ic+1]);
        }

        uint32_t sacc[2][8][2];
#pragma unroll
        for (int s = 0; s < 2; s++)
#pragma unroll
        for (int nb = 0; nb < 8; nb++) { sacc[s][nb][0]=0u; sacc[s][nb][1]=0u; }
#pragma unroll
        for (int kk = 0; kk < 4; kk++) {
#pragma unroll
            for (int p = 0; p < 4; p++) {
                uint32_t off = swz((uint32_t)((p*16 + ((lane>>4)&1)*8 + (lane&7))*128
                                              + kk*32 + ((lane>>3)&1)*16));
                uint32_t bh[4];
                ldsm4(bh, Au+OF_FQ+off);
                mma_h16(sacc[0][2*p],   ag[0][kk], &bh[0]);
                mma_h16(sacc[0][2*p+1], ag[0][kk], &bh[2]);
                mma_h16(sacc[1][2*p],   ag[1][kk], &bh[0]);
                mma_h16(sacc[1][2*p+1], ag[1][kk], &bh[2]);
            }
        }

        __syncthreads();   // all warps done reading f/L
        if (it+1 < it1) {  // prefetch f(it+1), L(it+1) while GEMM2 uses h
            const int i0 = (it+1)*64;
            const char* fq = (const char*)(g_fq + ((size_t)b*NPIX+i0)*CH);
            for (int q = t; q < 512; q += 64) CP16(Au+OF_FQ+swz(q*16), fq + q*16);
            if (t < 16) CP16(Au+OF_L + t*16, (const char*)(g_L + b*NPIX + i0) + t*16);
        }
        CPCOMMIT();
        CPWAIT(1); __syncthreads();   // h(it) ready; f(it+1) in flight

#pragma unroll
        for (int kk2 = 0; kk2 < 4; kk2++) {
            int nb0 = 2*kk2, nb1 = nb0+1;
            uint32_t aH0[4], aH1[4];
            aH0[0] = ex2h2(sub2(sacc[0][nb0][0], L2[nb0]));
            aH0[1] = ex2h2(sub2(sacc[0][nb0][1], L2[nb0]));
            aH0[2] = ex2h2(sub2(sacc[0][nb1][0], L2[nb1]));
            aH0[3] = ex2h2(sub2(sacc[0][nb1][1], L2[nb1]));
            aH1[0] = ex2h2(sub2(sacc[1][nb0][0], L2[nb0]));
            aH1[1] = ex2h2(sub2(sacc[1][nb0][1], L2[nb0]));
            aH1[2] = ex2h2(sub2(sacc[1][nb1][0], L2[nb1]));
            aH1[3] = ex2h2(sub2(sacc[1][nb1][1], L2[nb1]));
#pragma unroll
            for (int p = 0; p < 4; p++) {
                uint32_t off = swz((uint32_t)((p*16 + ((lane>>4)&1)*8 + (lane&7))*128
                                              + kk2*32 + ((lane>>3)&1)*16));
                uint32_t bh[4];
                ldsm4(bh, Au+OF_HH+off);
                mma_f16(oacc[0][2*p],   aH0, &bh[0]);
                mma_f16(oacc[0][2*p+1], aH0, &bh[2]);
                mma_f16(oacc[1][2*p],   aH1, &bh[0]);
                mma_f16(oacc[1][2*p+1], aH1, &bh[2]);
            }
        }

        __syncthreads();   // all warps done reading h
        if (it+1 < it1) {  // prefetch h(it+1)
            const int i0 = (it+1)*64;
            const char* hq = (const char*)(g_hq + (size_t)b*CH*NPIX + i0);
            for (int q = t; q < 512; q += 64)
                CP16(Au+OF_HH+swz(q*16), hq + (uint32_t)(q>>3)*NPIX*2 + (uint32_t)(q&7)*16);
        }
        CPCOMMIT();
    }

    // stage partial [64 c][64 j] fp32 in smem (reuses G+f regions), bulk-store
    CPWAIT(0); __syncthreads();
    float* outs = (float*)A;
#pragma unroll
    for (int s = 0; s < 2; s++) {
        const int jl = wid*32 + s*16 + (lane>>2);
#pragma unroll
        for (int nb = 0; nb < 8; nb++) {
            int c0 = nb*8 + (lane&3)*2;
            outs[c0*64 + jl]         = oacc[s][nb][0];
            outs[(c0+1)*64 + jl]     = oacc[s][nb][1];
            outs[c0*64 + jl + 8]     = oacc[s][nb][2];
            outs[(c0+1)*64 + jl + 8] = oacc[s][nb][3];
        }
    }
    __syncthreads();
    {
        float* pp = g_part + (((size_t)kv*BATCH + b)*64 + blockIdx.x)*4096;
        const float4* sp = (const float4*)outs;
        float4* dp = (float4*)pp;
        for (int q = t; q < 1024; q += 64) dp[q] = sp[q];
    }
}

// ---------------- Final epilogue: out = gamma*(p0+p1) + x --------------------
__global__ __launch_bounds__(256) void final_epi(
    const float* __restrict__ x, const float* __restrict__ gamma,
    float* __restrict__ out)
{
    const int t = threadIdx.x;
    const int b = blockIdx.y, jt = blockIdx.x;
    const float gam = *gamma;
    const float* p0 = g_part + (((size_t)0*BATCH + b)*64 + jt)*4096;
    const float* p1 = g_part + (((size_t)1*BATCH + b)*64 + jt)*4096;
    const int c = t>>2, seg = t&3;
    const int off = c*64 + seg*16;
    const float* xr   = x   + ((size_t)b*CH + c)*NPIX + jt*64 + seg*16;
    float*       orow = out + ((size_t)b*CH + c)*NPIX + jt*64 + seg*16;
#pragma unroll
    for (int u = 0; u < 4; u++) {
        float4 a = *(const float4*)(p0 + off + u*4);
        float4 bvec = *(const float4*)(p1 + off + u*4);
        float4 xv = *(const float4*)(xr + u*4);
        float4 r;
        r.x = gam*(a.x+bvec.x) + xv.x;
        r.y = gam*(a.y+bvec.y) + xv.y;
        r.z = gam*(a.z+bvec.z) + xv.z;
        r.w = gam*(a.w+bvec.w) + xv.w;
        *(float4*)(orow + u*4) = r;
    }
}

// -----------------------------------------------------------------------------
extern "C" void kernel_launch(void* const* d_in, const int* in_sizes, int n_in,
                              void* d_out, int out_size)
{
    const float* x     = (const float*)d_in[0];
    const float* Wf    = (const float*)d_in[1];
    const float* bf    = (const float*)d_in[2];
    const float* Wg    = (const float*)d_in[3];
    const float* bg    = (const float*)d_in[4];
    const float* Wh    = (const float*)d_in[5];
    const float* bh    = (const float*)d_in[6];
    const float* gamma = (const float*)d_in[7];
    float* out = (float*)d_out;
    (void)in_sizes; (void)n_in; (void)out_size;

    cudaFuncSetAttribute(fgh_hmma,   cudaFuncAttributeMaxDynamicSharedMemorySize, 41984+1024);
    cudaFuncSetAttribute(pass1_hmma, cudaFuncAttributeMaxDynamicSharedMemorySize, 24576+1024);
    cudaFuncSetAttribute(pass2_hmma, cudaFuncAttributeMaxDynamicSharedMemorySize, 24832+1024);

    prep_w<<<1, 256>>>(Wf, bf, Wg, bg, Wh, bh);
    fgh_hmma<<<dim3(64, BATCH), 128, 41984+1024>>>(x);
    pass1_hmma<<<dim3(64, BATCH, 2), 64, 24576+1024>>>();
    combine_L<<<BATCH*NPIX/256, 256>>>();
    pass2_hmma<<<dim3(64, BATCH, 2), 64, 24832+1024>>>();
    final_epi<<<dim3(64, BATCH), 256>>>(x, gamma, out);
}